// round 13
// baseline (speedup 1.0000x reference)
#include <cuda_runtime.h>
#include <cuda_bf16.h>
#include <cstdint>
#include <math.h>

// ---------------- problem constants ----------------
#define BB    1024
#define NH    2048
#define NR    16
#define NT    256
#define NIN   272           // NR + NT
#define NEXC  1638          // int(0.8*2048)
#define KTOT  2368          // 2048 + 256 + 16 + 48 pad = 37*64
#define NCHUNK 37
#define D0_CHUNKS 32        // chunks 0..31 -> rec accum, 32..36 -> inp+md_a accum
#define NOISE_COEF 0.22360679775f   // 0.5*sqrt(2*0.1)
#define JB_PER_ROW 296               // KTOT/8

// ---------------- scratch (__device__ globals; no allocation) ----------------
__device__ __align__(16) __nv_bfloat16 g_A[BB * KTOT];   // [h_post*ei | tuned | rule | 0]
__device__ __align__(16) __nv_bfloat16 g_W[NH * KTOT];   // [relu(rnnmat) | Win | Wmd_a | 0]

// ---------------- PTX helpers (sm_80-class only) ----------------
__device__ __forceinline__ uint32_t smem_u32(const void* p) {
    uint32_t a;
    asm("{ .reg .u64 t; cvta.to.shared.u64 t, %1; cvt.u32.u64 %0, t; }" : "=r"(a) : "l"(p));
    return a;
}
__device__ __forceinline__ uint32_t swz(uint32_t x) { return x ^ ((x >> 3) & 0x70); }

#define CP_ASYNC16(dst, src) \
    asm volatile("cp.async.cg.shared.global [%0], [%1], 16;" :: "r"(dst), "l"(src))
#define CP_COMMIT() asm volatile("cp.async.commit_group;" ::: "memory")
#define CP_WAIT(n)  asm volatile("cp.async.wait_group %0;" :: "n"(n) : "memory")

#define LDSM_X4(r0, r1, r2, r3, addr) \
    asm volatile("ldmatrix.sync.aligned.m8n8.x4.shared.b16 {%0,%1,%2,%3}, [%4];" \
                 : "=r"(r0), "=r"(r1), "=r"(r2), "=r"(r3) : "r"(addr))

#define MMA_BF16(d, a, b) \
    asm volatile("mma.sync.aligned.m16n8k16.row.col.f32.bf16.bf16.f32 " \
                 "{%0,%1,%2,%3}, {%4,%5,%6,%7}, {%8,%9}, {%0,%1,%2,%3};" \
                 : "+f"((d)[0]), "+f"((d)[1]), "+f"((d)[2]), "+f"((d)[3]) \
                 : "r"((a)[0]), "r"((a)[1]), "r"((a)[2]), "r"((a)[3]), \
                   "r"((b)[0]), "r"((b)[1]))

__device__ __forceinline__ uint4 pack8_bf16(const float* v) {
    uint4 r;
    __nv_bfloat162 p0 = __floats2bfloat162_rn(v[0], v[1]);
    __nv_bfloat162 p1 = __floats2bfloat162_rn(v[2], v[3]);
    __nv_bfloat162 p2 = __floats2bfloat162_rn(v[4], v[5]);
    __nv_bfloat162 p3 = __floats2bfloat162_rn(v[6], v[7]);
    r.x = *(uint32_t*)&p0; r.y = *(uint32_t*)&p1;
    r.z = *(uint32_t*)&p2; r.w = *(uint32_t*)&p3;
    return r;
}

// ---------------- merged prep kernel: W + A regions only (mdx moved to gemm) ----------------
#define W_BLOCKS (NH * JB_PER_ROW / 512)          // 1184
#define A_BLOCKS (BB * JB_PER_ROW / 512)          // 592
#define PREP_BLOCKS (W_BLOCKS + A_BLOCKS)

__global__ void __launch_bounds__(256) prep_kernel(
        const float* __restrict__ inputs, const float* __restrict__ prev_h,
        const float* __restrict__ syn_x, const float* __restrict__ syn_u,
        const float* __restrict__ rnnmat, const float* __restrict__ Win,
        const float* __restrict__ Wmd_a,
        float* __restrict__ out) {
    int bid = blockIdx.x;
    if (bid < W_BLOCKS) {
        #pragma unroll
        for (int rep = 0; rep < 2; rep++) {
            int idx = bid * 512 + rep * 256 + threadIdx.x;   // NH * 296
            int i = idx / JB_PER_ROW;
            int jb = idx - i * JB_PER_ROW;
            int j = jb * 8;
            float v[8];
            if (jb < 256) {                                   // relu(rnnmat)
                const float4* s = (const float4*)(rnnmat + (size_t)i * NH + j);
                float4 a = s[0], b = s[1];
                v[0]=fmaxf(a.x,0.f); v[1]=fmaxf(a.y,0.f); v[2]=fmaxf(a.z,0.f); v[3]=fmaxf(a.w,0.f);
                v[4]=fmaxf(b.x,0.f); v[5]=fmaxf(b.y,0.f); v[6]=fmaxf(b.z,0.f); v[7]=fmaxf(b.w,0.f);
            } else if (jb < 288) {                            // Win
                const float4* s = (const float4*)(Win + (size_t)i * NT + (j - NH));
                float4 a = s[0], b = s[1];
                v[0]=a.x; v[1]=a.y; v[2]=a.z; v[3]=a.w; v[4]=b.x; v[5]=b.y; v[6]=b.z; v[7]=b.w;
            } else if (jb < 290) {                            // Wmd_a
                const float4* s = (const float4*)(Wmd_a + (size_t)i * NR + (j - NH - NT));
                float4 a = s[0], b = s[1];
                v[0]=a.x; v[1]=a.y; v[2]=a.z; v[3]=a.w; v[4]=b.x; v[5]=b.y; v[6]=b.z; v[7]=b.w;
            } else {
                #pragma unroll
                for (int t = 0; t < 8; t++) v[t] = 0.0f;
            }
            *(uint4*)(g_W + (size_t)i * KTOT + j) = pack8_bf16(v);
        }
    } else {
        #pragma unroll
        for (int rep = 0; rep < 2; rep++) {
            int idx = (bid - W_BLOCKS) * 512 + rep * 256 + threadIdx.x;  // BB * 296
            int b = idx / JB_PER_ROW;
            int jb = idx - b * JB_PER_ROW;
            int j = jb * 8;
            float v[8];
            if (jb < 256) {                                   // syn update + h_post*ei
                size_t off = (size_t)b * NH + j;
                const float4* sx4 = (const float4*)(syn_x + off);
                const float4* su4 = (const float4*)(syn_u + off);
                const float4* ph4 = (const float4*)(prev_h + off);
                float sx[8], su[8], ph[8], sc[8];
                *(float4*)(sx + 0) = sx4[0]; *(float4*)(sx + 4) = sx4[1];
                *(float4*)(su + 0) = su4[0]; *(float4*)(su + 4) = su4[1];
                *(float4*)(ph + 0) = ph4[0]; *(float4*)(ph + 4) = ph4[1];
                #pragma unroll
                for (int t = 0; t < 8; t++) {
                    float a_std = ((j + t) & 1) ? 0.00417f : 0.05f;
                    float sxn = sx[t] + a_std * (1.0f - sx[t]) - 0.01f * su[t] * sx[t] * ph[t];
                    float sxc = fminf(1.0f, fmaxf(0.0f, sxn));
                    sc[t] = sxc;
                    float hp = sxc * sxc * ph[t];
                    v[t] = ((j + t) >= NEXC) ? -hp : hp;
                }
                // streaming stores: these outputs are never re-read on device
                __stwt((float4*)(out + (size_t)BB * NH + off),     *(float4*)(sc + 0));
                __stwt((float4*)(out + (size_t)BB * NH + off + 4), *(float4*)(sc + 4));
                __stwt((float4*)(out + (size_t)2 * BB * NH + off),     *(float4*)(sc + 0));
                __stwt((float4*)(out + (size_t)2 * BB * NH + off + 4), *(float4*)(sc + 4));
            } else if (jb < 288) {                            // tuned
                const float4* s = (const float4*)(inputs + (size_t)b * NIN + NR + (j - NH));
                float4 a = s[0], c = s[1];
                v[0]=a.x; v[1]=a.y; v[2]=a.z; v[3]=a.w; v[4]=c.x; v[5]=c.y; v[6]=c.z; v[7]=c.w;
            } else if (jb < 290) {                            // rule
                const float4* s = (const float4*)(inputs + (size_t)b * NIN + (j - NH - NT));
                float4 a = s[0], c = s[1];
                v[0]=a.x; v[1]=a.y; v[2]=a.z; v[3]=a.w; v[4]=c.x; v[5]=c.y; v[6]=c.z; v[7]=c.w;
            } else {
                #pragma unroll
                for (int t = 0; t < 8; t++) v[t] = 0.0f;
            }
            *(uint4*)(g_A + (size_t)b * KTOT + j) = pack8_bf16(v);
        }
    }
}

// ---------------- GEMM kernel: tile 128x64, 256 thr, 2 CTAs/SM, 4-buf ring ----------------
#define CHUNK_BYTES 24576            // A 16KB (128 rows) + W 8KB (64 rows)
#define SMEM_DATA_OFF 1024
#define RW_OFF (SMEM_DATA_OFF + 4 * CHUNK_BYTES)         // 99328: rule[128][16] + wmdx[64][16]
#define SMEM_BYTES (RW_OFF + 8192 + 4096)                // 111616 (x2 CTA = 223KB < 228KB)
#define NTHREADS 256

__device__ __forceinline__ void load_chunk(int c, int tid, int m0, int n0, uint32_t sb) {
    uint32_t base = sb + SMEM_DATA_OFF + (uint32_t)(c & 3) * CHUNK_BYTES;
    const __nv_bfloat16* gA = g_A + (size_t)m0 * KTOT + (size_t)c * 64;
    const __nv_bfloat16* gW = g_W + (size_t)n0 * KTOT + (size_t)c * 64;
    #pragma unroll
    for (int p = 0; p < 6; p++) {
        int q = p * NTHREADS + tid;     // 0..1535 : 1024 A segs + 512 W segs of 16B
        int isW = q >> 10;
        int qq = isW ? (q - 1024) : q;
        int row = qq >> 3;
        int seg = qq & 7;
        const __nv_bfloat16* src = (isW ? gW : gA) + (size_t)row * KTOT + seg * 8;
        uint32_t dst = base + (isW ? 16384u : 0u) + swz((uint32_t)(row * 128 + seg * 16));
        CP_ASYNC16(dst, src);
    }
    CP_COMMIT();
}

// one 64-wide K chunk, warp tile 32x32 (2 M-frags x 4 N-frags)
#define COMPUTE_CHUNK(ACC, bufA, bufW)                                          \
    do {                                                                        \
        _Pragma("unroll")                                                       \
        for (int ks = 0; ks < 4; ks++) {                                        \
            uint32_t af[2][4];                                                  \
            uint32_t bf[4][2];                                                  \
            _Pragma("unroll")                                                   \
            for (int mi = 0; mi < 2; mi++) {                                    \
                uint32_t row = (uint32_t)(mwarp + mi * 16 + (lane & 15));       \
                uint32_t cb  = (uint32_t)(ks * 32 + ((lane >> 4) << 4));        \
                LDSM_X4(af[mi][0], af[mi][1], af[mi][2], af[mi][3],             \
                        (bufA) + swz(row * 128 + cb));                          \
            }                                                                   \
            _Pragma("unroll")                                                   \
            for (int np = 0; np < 2; np++) {                                    \
                uint32_t nrow = (uint32_t)(nwarp + np * 16 + (lane & 7) + ((lane & 16) >> 1)); \
                uint32_t cb   = (uint32_t)(ks * 32 + ((lane & 8) << 1));        \
                LDSM_X4(bf[np*2][0], bf[np*2][1], bf[np*2+1][0], bf[np*2+1][1], \
                        (bufW) + swz(nrow * 128 + cb));                         \
            }                                                                   \
            _Pragma("unroll")                                                   \
            for (int mi = 0; mi < 2; mi++) {                                    \
                _Pragma("unroll")                                               \
                for (int ni = 0; ni < 4; ni++) {                                \
                    MMA_BF16(ACC[mi][ni], af[mi], bf[ni]);                      \
                }                                                               \
            }                                                                   \
        }                                                                       \
    } while (0)

__global__ void __launch_bounds__(NTHREADS, 2)
gemm_kernel(const float* __restrict__ prev_h, const float* __restrict__ noise,
            const float* __restrict__ inputs, const float* __restrict__ Wmd_x,
            float* __restrict__ out) {
    extern __shared__ char smem[];
    uint32_t sb = smem_u32(smem);
    int tid = threadIdx.x;
    int wid = tid >> 5;
    int lane = tid & 31;
    int m0 = (int)(blockIdx.x >> 5) * 128;   // 8 M tiles of 128
    int n0 = (int)(blockIdx.x & 31) * 64;    // 32 N tiles of 64
    int mwarp = (wid >> 1) * 32;             // 4 warp rows of 32
    int nwarp = (wid & 1) * 32;              // 2 warp cols of 32

    float accA[2][4][4];   // rec        (chunks 0..31)
    float accB[2][4][4];   // inp + md_a (chunks 32..36)
    #pragma unroll
    for (int i = 0; i < 2; i++)
        #pragma unroll
        for (int j = 0; j < 4; j++)
            #pragma unroll
            for (int k = 0; k < 4; k++) { accA[i][j][k] = 0.0f; accB[i][j][k] = 0.0f; }

    // prologue: 3 chunks in flight
    load_chunk(0, tid, m0, n0, sb);
    load_chunk(1, tid, m0, n0, sb);
    load_chunk(2, tid, m0, n0, sb);

    // stage mdx factors into smem (overlaps with cp.async prologue)
    // rule_s[128][16] f32 at RW_OFF; wmdx_s[64][16] f32 at RW_OFF+8192
    #pragma unroll
    for (int rep = 0; rep < 2; rep++) {
        int q = rep * NTHREADS + tid;            // 0..511
        int row = q >> 2, rg = q & 3;
        float4 v = *(const float4*)(inputs + (size_t)(m0 + row) * NIN + rg * 4);
        *(float4*)(smem + RW_OFF + row * 64 + rg * 16) = v;
    }
    {
        int q = tid;                             // 0..255
        int row = q >> 2, rg = q & 3;
        float4 v = *(const float4*)(Wmd_x + (size_t)(n0 + row) * NR + rg * 4);
        *(float4*)(smem + RW_OFF + 8192 + row * 64 + rg * 16) = v;
    }

    for (int c = 0; c < NCHUNK; c++) {
        if (c <= NCHUNK - 3)      { CP_WAIT(2); }
        else if (c == NCHUNK - 2) { CP_WAIT(1); }
        else                      { CP_WAIT(0); }
        __syncthreads();
        if (c + 3 < NCHUNK) load_chunk(c + 3, tid, m0, n0, sb);

        uint32_t bufA = sb + SMEM_DATA_OFF + (uint32_t)(c & 3) * CHUNK_BYTES;
        uint32_t bufW = bufA + 16384u;
        if (c < D0_CHUNKS) COMPUTE_CHUNK(accA, bufA, bufW);
        else               COMPUTE_CHUNK(accB, bufA, bufW);
    }

    // ---------------- epilogue (mdx = 1 + rule . wmdx computed in-place) ----------------
    #pragma unroll
    for (int mi = 0; mi < 2; mi++) {
        #pragma unroll
        for (int half = 0; half < 2; half++) {
            int rl = mwarp + mi * 16 + (lane >> 2) + half * 8;   // local row 0..127
            float ru[16];
            *(float4*)(ru + 0)  = *(const float4*)(smem + RW_OFF + rl * 64 + 0);
            *(float4*)(ru + 4)  = *(const float4*)(smem + RW_OFF + rl * 64 + 16);
            *(float4*)(ru + 8)  = *(const float4*)(smem + RW_OFF + rl * 64 + 32);
            *(float4*)(ru + 12) = *(const float4*)(smem + RW_OFF + rl * 64 + 48);
            int row = m0 + rl;
            const float* nsrow  = noise  + (size_t)row * NH;
            const float* phrow  = prev_h + (size_t)row * NH;
            float* orow = out + (size_t)row * NH;
            #pragma unroll
            for (int ni = 0; ni < 4; ni++) {
                int cl = nwarp + ni * 8 + (lane & 3) * 2;        // local col 0..63
                const float* w0 = (const float*)(smem + RW_OFF + 8192 + cl * 64);
                const float* w1 = w0 + 16;
                float mdx0 = 1.0f, mdx1 = 1.0f;
                #pragma unroll
                for (int r = 0; r < 16; r++) {
                    mdx0 += ru[r] * w0[r];
                    mdx1 += ru[r] * w1[r];
                }
                int cn = n0 + cl;
                float rec0 = accA[mi][ni][half * 2];
                float rec1 = accA[mi][ni][half * 2 + 1];
                float oth0 = accB[mi][ni][half * 2];
                float oth1 = accB[mi][ni][half * 2 + 1];
                float2 ns2  = *(const float2*)(nsrow + cn);
                float2 ph2  = *(const float2*)(phrow + cn);
                float dh0 = mdx0 * rec0 + oth0 + NOISE_COEF * ns2.x;
                float dh1 = mdx1 * rec1 + oth1 + NOISE_COEF * ns2.y;
                float2 o;
                o.x = 0.9f * ph2.x + 0.1f * fmaxf(tanhf(dh0), 0.0f);
                o.y = 0.9f * ph2.y + 0.1f * fmaxf(tanhf(dh1), 0.0f);
                *(float2*)(orow + cn) = o;
            }
        }
    }
}

// ---------------- launch ----------------
extern "C" void kernel_launch(void* const* d_in, const int* in_sizes, int n_in,
                              void* d_out, int out_size) {
    const float* inputs = (const float*)d_in[0];
    const float* prev_h = (const float*)d_in[1];
    const float* syn_x  = (const float*)d_in[2];
    const float* syn_u  = (const float*)d_in[3];
    const float* noise  = (const float*)d_in[4];
    const float* rnnmat = (const float*)d_in[5];
    const float* Win    = (const float*)d_in[6];
    const float* Wmd_x  = (const float*)d_in[7];
    const float* Wmd_a  = (const float*)d_in[8];
    float* out = (float*)d_out;

    prep_kernel<<<PREP_BLOCKS, 256>>>(inputs, prev_h, syn_x, syn_u,
                                      rnnmat, Win, Wmd_a, out);

    cudaFuncSetAttribute(gemm_kernel, cudaFuncAttributeMaxDynamicSharedMemorySize, SMEM_BYTES);
    gemm_kernel<<<256, NTHREADS, SMEM_BYTES>>>(prev_h, noise, inputs, Wmd_x, out);
}

// round 14
// speedup vs baseline: 1.1671x; 1.1671x over previous
#include <cuda_runtime.h>
#include <cuda_bf16.h>
#include <cstdint>
#include <math.h>

// ---------------- problem constants ----------------
#define BB    1024
#define NH    2048
#define NR    16
#define NT    256
#define NIN   272           // NR + NT
#define NEXC  1638          // int(0.8*2048)
#define KTOT  2368          // 2048 + 256 + 16 + 48 pad = 37*64
#define NCHUNK 37
#define D0_CHUNKS 32        // chunks 0..31 -> rec accum, 32..36 -> inp+md_a accum
#define NOISE_COEF 0.22360679775f   // 0.5*sqrt(2*0.1)
#define JB_PER_ROW 296               // KTOT/8

// ---------------- scratch (__device__ globals; no allocation) ----------------
__device__ __align__(16) __nv_bfloat16 g_A[BB * KTOT];   // [h_post*ei | tuned | rule | 0]
__device__ __align__(16) __nv_bfloat16 g_W[NH * KTOT];   // [relu(rnnmat) | Win | Wmd_a | 0]
__device__ __align__(16) float g_mdx1[BB * NH];          // 1 + md_x

// ---------------- PTX helpers (sm_80-class only) ----------------
__device__ __forceinline__ uint32_t smem_u32(const void* p) {
    uint32_t a;
    asm("{ .reg .u64 t; cvta.to.shared.u64 t, %1; cvt.u32.u64 %0, t; }" : "=r"(a) : "l"(p));
    return a;
}
__device__ __forceinline__ uint32_t swz(uint32_t x) { return x ^ ((x >> 3) & 0x70); }

#define CP_ASYNC16(dst, src) \
    asm volatile("cp.async.cg.shared.global [%0], [%1], 16;" :: "r"(dst), "l"(src))
#define CP_COMMIT() asm volatile("cp.async.commit_group;" ::: "memory")
#define CP_WAIT(n)  asm volatile("cp.async.wait_group %0;" :: "n"(n) : "memory")

#define LDSM_X4(r0, r1, r2, r3, addr) \
    asm volatile("ldmatrix.sync.aligned.m8n8.x4.shared.b16 {%0,%1,%2,%3}, [%4];" \
                 : "=r"(r0), "=r"(r1), "=r"(r2), "=r"(r3) : "r"(addr))

#define MMA_BF16(d, a, b) \
    asm volatile("mma.sync.aligned.m16n8k16.row.col.f32.bf16.bf16.f32 " \
                 "{%0,%1,%2,%3}, {%4,%5,%6,%7}, {%8,%9}, {%0,%1,%2,%3};" \
                 : "+f"((d)[0]), "+f"((d)[1]), "+f"((d)[2]), "+f"((d)[3]) \
                 : "r"((a)[0]), "r"((a)[1]), "r"((a)[2]), "r"((a)[3]), \
                   "r"((b)[0]), "r"((b)[1]))

__device__ __forceinline__ uint4 pack8_bf16(const float* v) {
    uint4 r;
    __nv_bfloat162 p0 = __floats2bfloat162_rn(v[0], v[1]);
    __nv_bfloat162 p1 = __floats2bfloat162_rn(v[2], v[3]);
    __nv_bfloat162 p2 = __floats2bfloat162_rn(v[4], v[5]);
    __nv_bfloat162 p3 = __floats2bfloat162_rn(v[6], v[7]);
    r.x = *(uint32_t*)&p0; r.y = *(uint32_t*)&p1;
    r.z = *(uint32_t*)&p2; r.w = *(uint32_t*)&p3;
    return r;
}

// ---------------- merged prep kernel: 2 items per thread ----------------
#define W_BLOCKS (NH * JB_PER_ROW / 512)          // 1184
#define A_BLOCKS (BB * JB_PER_ROW / 512)          // 592
#define M_BLOCKS (NH * (BB / 4) / 512)            // 1024
#define PREP_BLOCKS (W_BLOCKS + A_BLOCKS + M_BLOCKS)

__global__ void __launch_bounds__(256) prep_kernel(
        const float* __restrict__ inputs, const float* __restrict__ prev_h,
        const float* __restrict__ syn_x, const float* __restrict__ syn_u,
        const float* __restrict__ rnnmat, const float* __restrict__ Win,
        const float* __restrict__ Wmd_x, const float* __restrict__ Wmd_a,
        float* __restrict__ out) {
    int bid = blockIdx.x;
    if (bid < W_BLOCKS) {
        #pragma unroll
        for (int rep = 0; rep < 2; rep++) {
            int idx = bid * 512 + rep * 256 + threadIdx.x;   // NH * 296
            int i = idx / JB_PER_ROW;
            int jb = idx - i * JB_PER_ROW;
            int j = jb * 8;
            float v[8];
            if (jb < 256) {                                   // relu(rnnmat)
                const float4* s = (const float4*)(rnnmat + (size_t)i * NH + j);
                float4 a = s[0], b = s[1];
                v[0]=fmaxf(a.x,0.f); v[1]=fmaxf(a.y,0.f); v[2]=fmaxf(a.z,0.f); v[3]=fmaxf(a.w,0.f);
                v[4]=fmaxf(b.x,0.f); v[5]=fmaxf(b.y,0.f); v[6]=fmaxf(b.z,0.f); v[7]=fmaxf(b.w,0.f);
            } else if (jb < 288) {                            // Win
                const float4* s = (const float4*)(Win + (size_t)i * NT + (j - NH));
                float4 a = s[0], b = s[1];
                v[0]=a.x; v[1]=a.y; v[2]=a.z; v[3]=a.w; v[4]=b.x; v[5]=b.y; v[6]=b.z; v[7]=b.w;
            } else if (jb < 290) {                            // Wmd_a
                const float4* s = (const float4*)(Wmd_a + (size_t)i * NR + (j - NH - NT));
                float4 a = s[0], b = s[1];
                v[0]=a.x; v[1]=a.y; v[2]=a.z; v[3]=a.w; v[4]=b.x; v[5]=b.y; v[6]=b.z; v[7]=b.w;
            } else {
                #pragma unroll
                for (int t = 0; t < 8; t++) v[t] = 0.0f;
            }
            *(uint4*)(g_W + (size_t)i * KTOT + j) = pack8_bf16(v);
        }
    } else if (bid < W_BLOCKS + A_BLOCKS) {
        #pragma unroll
        for (int rep = 0; rep < 2; rep++) {
            int idx = (bid - W_BLOCKS) * 512 + rep * 256 + threadIdx.x;  // BB * 296
            int b = idx / JB_PER_ROW;
            int jb = idx - b * JB_PER_ROW;
            int j = jb * 8;
            float v[8];
            if (jb < 256) {                                   // syn update + h_post*ei
                size_t off = (size_t)b * NH + j;
                const float4* sx4 = (const float4*)(syn_x + off);
                const float4* su4 = (const float4*)(syn_u + off);
                const float4* ph4 = (const float4*)(prev_h + off);
                float sx[8], su[8], ph[8], sc[8];
                *(float4*)(sx + 0) = sx4[0]; *(float4*)(sx + 4) = sx4[1];
                *(float4*)(su + 0) = su4[0]; *(float4*)(su + 4) = su4[1];
                *(float4*)(ph + 0) = ph4[0]; *(float4*)(ph + 4) = ph4[1];
                #pragma unroll
                for (int t = 0; t < 8; t++) {
                    float a_std = ((j + t) & 1) ? 0.00417f : 0.05f;
                    float sxn = sx[t] + a_std * (1.0f - sx[t]) - 0.01f * su[t] * sx[t] * ph[t];
                    float sxc = fminf(1.0f, fmaxf(0.0f, sxn));
                    sc[t] = sxc;
                    float hp = sxc * sxc * ph[t];
                    v[t] = ((j + t) >= NEXC) ? -hp : hp;
                }
                // streaming stores: these outputs are never re-read on device
                __stwt((float4*)(out + (size_t)BB * NH + off),     *(float4*)(sc + 0));
                __stwt((float4*)(out + (size_t)BB * NH + off + 4), *(float4*)(sc + 4));
                __stwt((float4*)(out + (size_t)2 * BB * NH + off),     *(float4*)(sc + 0));
                __stwt((float4*)(out + (size_t)2 * BB * NH + off + 4), *(float4*)(sc + 4));
            } else if (jb < 288) {                            // tuned
                const float4* s = (const float4*)(inputs + (size_t)b * NIN + NR + (j - NH));
                float4 a = s[0], c = s[1];
                v[0]=a.x; v[1]=a.y; v[2]=a.z; v[3]=a.w; v[4]=c.x; v[5]=c.y; v[6]=c.z; v[7]=c.w;
            } else if (jb < 290) {                            // rule
                const float4* s = (const float4*)(inputs + (size_t)b * NIN + (j - NH - NT));
                float4 a = s[0], c = s[1];
                v[0]=a.x; v[1]=a.y; v[2]=a.z; v[3]=a.w; v[4]=c.x; v[5]=c.y; v[6]=c.z; v[7]=c.w;
            } else {
                #pragma unroll
                for (int t = 0; t < 8; t++) v[t] = 0.0f;
            }
            *(uint4*)(g_A + (size_t)b * KTOT + j) = pack8_bf16(v);
        }
    } else {
        #pragma unroll
        for (int rep = 0; rep < 2; rep++) {
            int idx = (bid - W_BLOCKS - A_BLOCKS) * 512 + rep * 256 + threadIdx.x;  // NH * BB/4
            int i  = idx & (NH - 1);
            int bq = idx >> 11;
            int b0 = bq * 4;
            float w[16];
            const float4* ws = (const float4*)(Wmd_x + (size_t)i * NR);
            *(float4*)(w + 0)  = ws[0]; *(float4*)(w + 4)  = ws[1];
            *(float4*)(w + 8)  = ws[2]; *(float4*)(w + 12) = ws[3];
            #pragma unroll
            for (int k = 0; k < 4; k++) {
                const float* rule = inputs + (size_t)(b0 + k) * NIN;
                float acc = 1.0f;
                #pragma unroll
                for (int r = 0; r < NR; r++) acc += rule[r] * w[r];
                g_mdx1[(size_t)(b0 + k) * NH + i] = acc;
            }
        }
    }
}

// ---------------- GEMM kernel: tile 128x64, 256 thr, 2 CTAs/SM, 4-buf ring ----------------
#define CHUNK_BYTES 24576            // A 16KB (128 rows) + W 8KB (64 rows)
#define SMEM_DATA_OFF 1024
#define SMEM_BYTES (SMEM_DATA_OFF + 4 * CHUNK_BYTES)     // 99328
#define NTHREADS 256

__device__ __forceinline__ void load_chunk(int c, int tid, int m0, int n0, uint32_t sb) {
    uint32_t base = sb + SMEM_DATA_OFF + (uint32_t)(c & 3) * CHUNK_BYTES;
    const __nv_bfloat16* gA = g_A + (size_t)m0 * KTOT + (size_t)c * 64;
    const __nv_bfloat16* gW = g_W + (size_t)n0 * KTOT + (size_t)c * 64;
    #pragma unroll
    for (int p = 0; p < 6; p++) {
        int q = p * NTHREADS + tid;     // 0..1535 : 1024 A segs + 512 W segs of 16B
        int isW = q >> 10;
        int qq = isW ? (q - 1024) : q;
        int row = qq >> 3;
        int seg = qq & 7;
        const __nv_bfloat16* src = (isW ? gW : gA) + (size_t)row * KTOT + seg * 8;
        uint32_t dst = base + (isW ? 16384u : 0u) + swz((uint32_t)(row * 128 + seg * 16));
        CP_ASYNC16(dst, src);
    }
    CP_COMMIT();
}

// one 64-wide K chunk, warp tile 32x32 (2 M-frags x 4 N-frags)
#define COMPUTE_CHUNK(ACC, bufA, bufW)                                          \
    do {                                                                        \
        _Pragma("unroll")                                                       \
        for (int ks = 0; ks < 4; ks++) {                                        \
            uint32_t af[2][4];                                                  \
            uint32_t bf[4][2];                                                  \
            _Pragma("unroll")                                                   \
            for (int mi = 0; mi < 2; mi++) {                                    \
                uint32_t row = (uint32_t)(mwarp + mi * 16 + (lane & 15));       \
                uint32_t cb  = (uint32_t)(ks * 32 + ((lane >> 4) << 4));        \
                LDSM_X4(af[mi][0], af[mi][1], af[mi][2], af[mi][3],             \
                        (bufA) + swz(row * 128 + cb));                          \
            }                                                                   \
            _Pragma("unroll")                                                   \
            for (int np = 0; np < 2; np++) {                                    \
                uint32_t nrow = (uint32_t)(nwarp + np * 16 + (lane & 7) + ((lane & 16) >> 1)); \
                uint32_t cb   = (uint32_t)(ks * 32 + ((lane & 8) << 1));        \
                LDSM_X4(bf[np*2][0], bf[np*2][1], bf[np*2+1][0], bf[np*2+1][1], \
                        (bufW) + swz(nrow * 128 + cb));                         \
            }                                                                   \
            _Pragma("unroll")                                                   \
            for (int mi = 0; mi < 2; mi++) {                                    \
                _Pragma("unroll")                                               \
                for (int ni = 0; ni < 4; ni++) {                                \
                    MMA_BF16(ACC[mi][ni], af[mi], bf[ni]);                      \
                }                                                               \
            }                                                                   \
        }                                                                       \
    } while (0)

__global__ void __launch_bounds__(NTHREADS, 2)
gemm_kernel(const float* __restrict__ prev_h, const float* __restrict__ noise,
            float* __restrict__ out) {
    extern __shared__ char smem[];
    uint32_t sb = smem_u32(smem);
    int tid = threadIdx.x;
    int wid = tid >> 5;
    int lane = tid & 31;
    int m0 = (int)(blockIdx.x >> 5) * 128;   // 8 M tiles of 128
    int n0 = (int)(blockIdx.x & 31) * 64;    // 32 N tiles of 64
    int mwarp = (wid >> 1) * 32;             // 4 warp rows of 32
    int nwarp = (wid & 1) * 32;              // 2 warp cols of 32

    float accA[2][4][4];   // rec        (chunks 0..31)
    float accB[2][4][4];   // inp + md_a (chunks 32..36)
    #pragma unroll
    for (int i = 0; i < 2; i++)
        #pragma unroll
        for (int j = 0; j < 4; j++)
            #pragma unroll
            for (int k = 0; k < 4; k++) { accA[i][j][k] = 0.0f; accB[i][j][k] = 0.0f; }

    // prologue: 3 chunks in flight
    load_chunk(0, tid, m0, n0, sb);
    load_chunk(1, tid, m0, n0, sb);
    load_chunk(2, tid, m0, n0, sb);

    for (int c = 0; c < NCHUNK; c++) {
        if (c <= NCHUNK - 3)      { CP_WAIT(2); }
        else if (c == NCHUNK - 2) { CP_WAIT(1); }
        else                      { CP_WAIT(0); }
        __syncthreads();
        if (c + 3 < NCHUNK) load_chunk(c + 3, tid, m0, n0, sb);

        uint32_t bufA = sb + SMEM_DATA_OFF + (uint32_t)(c & 3) * CHUNK_BYTES;
        uint32_t bufW = bufA + 16384u;
        if (c < D0_CHUNKS) COMPUTE_CHUNK(accA, bufA, bufW);
        else               COMPUTE_CHUNK(accB, bufA, bufW);
    }

    // ---------------- epilogue ----------------
    #pragma unroll
    for (int mi = 0; mi < 2; mi++) {
        #pragma unroll
        for (int half = 0; half < 2; half++) {
            int row = m0 + mwarp + mi * 16 + (lane >> 2) + half * 8;
            const float* mdxrow = g_mdx1 + (size_t)row * NH;
            const float* nsrow  = noise  + (size_t)row * NH;
            const float* phrow  = prev_h + (size_t)row * NH;
            float* orow = out + (size_t)row * NH;
            #pragma unroll
            for (int ni = 0; ni < 4; ni++) {
                int cn = n0 + nwarp + ni * 8 + (lane & 3) * 2;
                float rec0 = accA[mi][ni][half * 2];
                float rec1 = accA[mi][ni][half * 2 + 1];
                float oth0 = accB[mi][ni][half * 2];
                float oth1 = accB[mi][ni][half * 2 + 1];
                float2 mdx2 = *(const float2*)(mdxrow + cn);
                float2 ns2  = *(const float2*)(nsrow + cn);
                float2 ph2  = *(const float2*)(phrow + cn);
                float dh0 = mdx2.x * rec0 + oth0 + NOISE_COEF * ns2.x;
                float dh1 = mdx2.y * rec1 + oth1 + NOISE_COEF * ns2.y;
                float2 o;
                o.x = 0.9f * ph2.x + 0.1f * fmaxf(tanhf(dh0), 0.0f);
                o.y = 0.9f * ph2.y + 0.1f * fmaxf(tanhf(dh1), 0.0f);
                __stwt((float2*)(orow + cn), o);   // h output: never re-read on device
            }
        }
    }
}

// ---------------- launch ----------------
extern "C" void kernel_launch(void* const* d_in, const int* in_sizes, int n_in,
                              void* d_out, int out_size) {
    const float* inputs = (const float*)d_in[0];
    const float* prev_h = (const float*)d_in[1];
    const float* syn_x  = (const float*)d_in[2];
    const float* syn_u  = (const float*)d_in[3];
    const float* noise  = (const float*)d_in[4];
    const float* rnnmat = (const float*)d_in[5];
    const float* Win    = (const float*)d_in[6];
    const float* Wmd_x  = (const float*)d_in[7];
    const float* Wmd_a  = (const float*)d_in[8];
    float* out = (float*)d_out;

    prep_kernel<<<PREP_BLOCKS, 256>>>(inputs, prev_h, syn_x, syn_u,
                                      rnnmat, Win, Wmd_x, Wmd_a, out);

    cudaFuncSetAttribute(gemm_kernel, cudaFuncAttributeMaxDynamicSharedMemorySize, SMEM_BYTES);
    gemm_kernel<<<256, NTHREADS, SMEM_BYTES>>>(prev_h, noise, out);
}